// round 16
// baseline (speedup 1.0000x reference)
#include <cuda_runtime.h>
#include <cstdint>

// DiverseSiblingsSearch on GB300 — split-row formulation: 1280 half-row blocks
// (2x parallelism, half the per-CTA runtime/spread), seg1-sampled threshold per
// half, exact half-top-10, fused per-batch merge finisher. Single DRAM pass.
// lprobs: (128, 5, 50257) f32, scores: (128, 5, 10) f32, step: int scalar (=10).
// Output (f32): final_scores (128,10) | final_indices (128,10) | final_beams (128,10).

#define BSZ     128
#define BEAM    5
#define VOCAB   50257
#define KSEL    10
#define ROWS    (BSZ * BEAM)
#define SPLIT   2
#define HLEN    25129                  // ceil(VOCAB/2); half1 gets 25128
#define T       128
#define NWARP   (T / 32)               // 4
#define NQ1     12                     // seg1 = 12 quads/thread = 6144 elems of segment
#define CAP     512
#define DIV_RATE 0.5f
#define NEG_INF __int_as_float(0xff800000u)
#define IDX_INF 0x7fffffff

// Inter-block scratch (no allocations allowed).
__device__ float g_half_val[ROWS * SPLIT * KSEL];   // raw lprob values, rank-sorted
__device__ int   g_half_idx[ROWS * SPLIT * KSEL];   // global vocab indices
__device__ int   g_batch_done[BSZ];                 // zero-init; reset each replay

__device__ __forceinline__ bool better(float v1, int i1, float v2, int i2) {
    // JAX top_k stability: larger value wins; ties -> smaller index wins.
    return (v1 > v2) || (v1 == v2 && i1 < i2);
}

__device__ __forceinline__ float4 max4(float4 a, float4 b) {
    return make_float4(fmaxf(a.x, b.x), fmaxf(a.y, b.y), fmaxf(a.z, b.z), fmaxf(a.w, b.w));
}

__global__ __launch_bounds__(T, 10)
void dss_kernel(const float* __restrict__ lprobs,
                const float* __restrict__ scores,
                const int* __restrict__ step_ptr,
                int score_last_dim,
                float* __restrict__ out) {
    __shared__ float    swtop[3 * NWARP];
    __shared__ float    sthr;
    __shared__ unsigned scount;
    __shared__ float    cval[CAP];
    __shared__ int      cidx[CAP];

    const int bx    = blockIdx.x;
    const int row   = bx / SPLIT;               // row = batch * BEAM + beam
    const int half  = bx % SPLIT;
    const int batch = row / BEAM;
    const int tid   = threadIdx.x;
    const int lane  = tid & 31;
    const int wid   = tid >> 5;

    const int seg0    = half * HLEN;
    const int seg_len = min(VOCAB - seg0, HLEN);
    const float* __restrict__ sp = lprobs + (size_t)row * VOCAB + seg0;

    if (tid == 0) scount = 0u;

    // Alignment peel for this segment: (row*VOCAB + seg0) mod 4 == (row+half) mod 4.
    const int P     = (4 - ((row + half) & 3)) & 3;
    const int nv    = (seg_len - P) >> 2;        // aligned float4 count (~6281)
    const int tailn = (seg_len - P) & 3;
    const float4* __restrict__ sp4 = reinterpret_cast<const float4*>(sp + P);

    // ---- Phase 1a: branchless max over seg1 (first NQ1 quads/thread) ----
    float4 M0 = make_float4(NEG_INF, NEG_INF, NEG_INF, NEG_INF);
    float4 M1 = M0, M2 = M0, M3 = M0;
#pragma unroll
    for (int j = 0; j < NQ1; j += 4) {
        float4 a = sp4[tid + j * T];
        float4 b = sp4[tid + (j + 1) * T];
        float4 c = sp4[tid + (j + 2) * T];
        float4 d = sp4[tid + (j + 3) * T];
        M0 = max4(M0, a); M1 = max4(M1, b); M2 = max4(M2, c); M3 = max4(M3, d);
    }
    M0 = max4(max4(M0, M1), max4(M2, M3));
    float m = fmaxf(fmaxf(M0.x, M0.y), fmaxf(M0.z, M0.w));

    // ---- Per-warp top-3 of per-thread seg1 maxima (3 distinct elements/warp) ----
    {
        float x = m;
        float w1 = x;
        for (int off = 16; off; off >>= 1) w1 = fmaxf(w1, __shfl_xor_sync(0xffffffffu, w1, off));
        unsigned h1 = __ballot_sync(0xffffffffu, x == w1);
        if (lane == __ffs(h1) - 1) x = NEG_INF;
        float w2 = x;
        for (int off = 16; off; off >>= 1) w2 = fmaxf(w2, __shfl_xor_sync(0xffffffffu, w2, off));
        unsigned h2 = __ballot_sync(0xffffffffu, x == w2);
        if (lane == __ffs(h2) - 1) x = NEG_INF;
        float w3 = x;
        for (int off = 16; off; off >>= 1) w3 = fmaxf(w3, __shfl_xor_sync(0xffffffffu, w3, off));
        if (lane == 0) { swtop[wid] = w1; swtop[NWARP + wid] = w2; swtop[2 * NWARP + wid] = w3; }
    }
    __syncthreads();

    // ---- thr = 10th largest of 12 distinct seg1 elements (subset of segment
    // => thr <= segment's true 10th largest: conservative, >=10 survivors). ----
    if (tid < 32) {
        float x = (lane < 3 * NWARP) ? swtop[lane] : NEG_INF;
        float t = NEG_INF;
        for (int r = 0; r < KSEL; ++r) {
            float bv = x;
            for (int off = 16; off; off >>= 1) bv = fmaxf(bv, __shfl_xor_sync(0xffffffffu, bv, off));
            unsigned holders = __ballot_sync(0xffffffffu, x == bv);
            if (lane == __ffs(holders) - 1) x = NEG_INF;   // retire one instance
            t = bv;
        }
        if (lane == 0) sthr = t;
    }
    __syncthreads();
    const float thr = sthr;

    // Quad filter: prefilter on quad max, push survivors (exact value + GLOBAL index).
    auto filter_quad = [&](float4 a, int i0) {
        float qm = fmaxf(fmaxf(a.x, a.y), fmaxf(a.z, a.w));
        if (qm >= thr) {                        // rare
            if (a.x >= thr) { unsigned p = atomicAdd(&scount, 1u); if (p < CAP) { cval[p] = a.x; cidx[p] = i0; } }
            if (a.y >= thr) { unsigned p = atomicAdd(&scount, 1u); if (p < CAP) { cval[p] = a.y; cidx[p] = i0 + 1; } }
            if (a.z >= thr) { unsigned p = atomicAdd(&scount, 1u); if (p < CAP) { cval[p] = a.z; cidx[p] = i0 + 2; } }
            if (a.w >= thr) { unsigned p = atomicAdd(&scount, 1u); if (p < CAP) { cval[p] = a.w; cidx[p] = i0 + 3; } }
        }
    };

    // ---- Phase 2: one filtered pass over the ENTIRE segment (seg1 hits L1/L2) ----
    {
        int v = tid;
        for (; v + 3 * T < nv; v += 4 * T) {
            float4 a = sp4[v];
            float4 b = sp4[v + T];
            float4 c = sp4[v + 2 * T];
            float4 d = sp4[v + 3 * T];
            filter_quad(a, seg0 + P + 4 * v);
            filter_quad(b, seg0 + P + 4 * (v + T));
            filter_quad(c, seg0 + P + 4 * (v + 2 * T));
            filter_quad(d, seg0 + P + 4 * (v + 3 * T));
        }
        for (; v < nv; v += T) filter_quad(sp4[v], seg0 + P + 4 * v);
    }
    if (tid == 0) {          // head elements, exact test
        for (int i = 0; i < P; ++i) {
            float x = sp[i];
            if (x >= thr) { unsigned p = atomicAdd(&scount, 1u); if (p < CAP) { cval[p] = x; cidx[p] = seg0 + i; } }
        }
    }
    if (tid == 1) {          // tail elements, exact test
        for (int q = 0; q < tailn; ++q) {
            int i = P + 4 * nv + q;
            float x = sp[i];
            if (x >= thr) { unsigned p = atomicAdd(&scount, 1u); if (p < CAP) { cval[p] = x; cidx[p] = seg0 + i; } }
        }
    }
    __syncthreads();

    const unsigned cnt = scount;
    const int hslot = (row * SPLIT + half) * KSEL;

    if (cnt > CAP) {
        // Pathological mass-tie fallback: exact serial top-10 over this segment.
        if (tid == 0) {
            float val[KSEL]; int idq[KSEL];
#pragma unroll
            for (int q = 0; q < KSEL; ++q) { val[q] = NEG_INF; idq[q] = IDX_INF; }
            for (int i = 0; i < seg_len; ++i) {
                float x = sp[i];
                int  gi = seg0 + i;
                if (better(x, gi, val[KSEL - 1], idq[KSEL - 1])) {
                    val[KSEL - 1] = x; idq[KSEL - 1] = gi;
#pragma unroll
                    for (int q = KSEL - 1; q > 0; --q) {
                        if (better(val[q], idq[q], val[q - 1], idq[q - 1])) {
                            float tv = val[q]; val[q] = val[q - 1]; val[q - 1] = tv;
                            int   ti = idq[q]; idq[q] = idq[q - 1]; idq[q - 1] = ti;
                        }
                    }
                }
            }
#pragma unroll
            for (int r = 0; r < KSEL; ++r) { g_half_val[hslot + r] = val[r]; g_half_idx[hslot + r] = idq[r]; }
        }
    } else {
        // Warp-parallel stable top-10 over candidates; emit RAW values (rank-sorted).
        if (tid < 32) {
            for (int r = 0; r < KSEL; ++r) {
                float bv = NEG_INF; int bi = IDX_INF; int bp = -1;
                for (unsigned c = lane; c < cnt; c += 32) {
                    float x = cval[c]; int ix = cidx[c];
                    if (better(x, ix, bv, bi)) { bv = x; bi = ix; bp = (int)c; }
                }
                for (int off = 16; off; off >>= 1) {
                    float ov = __shfl_down_sync(0xffffffffu, bv, off);
                    int   oi = __shfl_down_sync(0xffffffffu, bi, off);
                    int   op = __shfl_down_sync(0xffffffffu, bp, off);
                    if (better(ov, oi, bv, bi)) { bv = ov; bi = oi; bp = op; }
                }
                if (lane == 0) {
                    g_half_val[hslot + r] = bv;
                    g_half_idx[hslot + r] = bi;
                    cval[bp] = NEG_INF; cidx[bp] = IDX_INF;
                }
                __syncwarp();
            }
        }
    }

    // ---- Fused finisher: last of the batch's BEAM*SPLIT=10 half-blocks ----
    int done = 0;
    if (tid == 0) {
        __threadfence();                              // release g_half writes
        done = atomicAdd(&g_batch_done[batch], 1);
    }
    if (tid < 32) {
        done = __shfl_sync(0xffffffffu, done, 0);
        if (done == BEAM * SPLIT - 1) {
            __threadfence();                          // acquire peers' g_half
            const int stepv = step_ptr ? *step_ptr : KSEL;

            // Per row: top-10 of its 2x10 half candidates; apply base+penalty
            // in reference op order; store 50 row candidates in smem (reuse cval).
            for (int br = 0; br < BEAM; ++br) {
                const int r0  = (batch * BEAM + br);
                const float base = scores[r0 * score_last_dim + (stepv - 1)];
                float v = NEG_INF; int ix = IDX_INF;
                if (lane < SPLIT * KSEL) {
                    v  = __ldcg(&g_half_val[r0 * SPLIT * KSEL + lane]);
                    ix = __ldcg(&g_half_idx[r0 * SPLIT * KSEL + lane]);
                }
                for (int r = 0; r < KSEL; ++r) {
                    float bv = v; int bi = ix;
                    for (int off = 16; off; off >>= 1) {
                        float ov = __shfl_xor_sync(0xffffffffu, bv, off);
                        int   oi = __shfl_xor_sync(0xffffffffu, bi, off);
                        if (better(ov, oi, bv, bi)) { bv = ov; bi = oi; }
                    }
                    unsigned holders = __ballot_sync(0xffffffffu, (v == bv) && (ix == bi));
                    if (lane == __ffs(holders) - 1) { v = NEG_INF; ix = IDX_INF; }
                    if (lane == 0) {
                        // ((lprob + base) - penalty): reference op order -> bit-exact.
                        cval[br * KSEL + r] = (bv + base) - (float)(r + 1) * DIV_RATE;
                        cidx[br * KSEL + r] = bi;
                    }
                }
            }
            __syncwarp();

            // Final stable top-10 over 50 (flat position = br*10 + rank).
            float v0 = NEG_INF, v1 = NEG_INF;
            int   p0 = IDX_INF, p1 = IDX_INF;
            if (lane < BEAM * KSEL)      { v0 = cval[lane];      p0 = lane; }
            if (lane + 32 < BEAM * KSEL) { v1 = cval[lane + 32]; p1 = lane + 32; }
            for (int r = 0; r < KSEL; ++r) {
                float bv; int bp;
                if (better(v0, p0, v1, p1)) { bv = v0; bp = p0; } else { bv = v1; bp = p1; }
                for (int off = 16; off; off >>= 1) {
                    float ov = __shfl_down_sync(0xffffffffu, bv, off);
                    int   op = __shfl_down_sync(0xffffffffu, bp, off);
                    if (better(ov, op, bv, bp)) { bv = ov; bp = op; }
                }
                bv = __shfl_sync(0xffffffffu, bv, 0);
                bp = __shfl_sync(0xffffffffu, bp, 0);
                if (lane == 0) {
                    out[batch * KSEL + r]                  = bv;                  // scores
                    out[BSZ * KSEL + batch * KSEL + r]     = (float)cidx[bp];     // indices
                    out[2 * BSZ * KSEL + batch * KSEL + r] = (float)(bp / KSEL);  // beams
                }
                if (p0 == bp) { v0 = NEG_INF; p0 = IDX_INF; }
                if (p1 == bp) { v1 = NEG_INF; p1 = IDX_INF; }
            }
            if (lane == 0) atomicExch(&g_batch_done[batch], 0);   // reset for next replay
        }
    }
}

extern "C" void kernel_launch(void* const* d_in, const int* in_sizes, int n_in,
                              void* d_out, int out_size) {
    const float* lprobs = (const float*)d_in[0];
    const float* scores = (const float*)d_in[1];
    const int*   step   = (n_in >= 3) ? (const int*)d_in[2] : nullptr;
    const int score_last_dim = in_sizes[1] / ROWS;   // = 10

    dss_kernel<<<ROWS * SPLIT, T>>>(lprobs, scores, step, score_last_dim, (float*)d_out);
}